// round 5
// baseline (speedup 1.0000x reference)
#include <cuda_runtime.h>

// Scratch: j-reduced weights and squashed per-batch output row.
__device__ float g_wsum[256 * 256];   // Wsum[m][k] = sum_j W[j][m][k]
__device__ float g_o[512 * 256];      // o[b][k] = squash_k(sum_m in[b,m]*Wsum[m,k]/256)

// ---------------------------------------------------------------------------
// Kernel A: Wsum[m,k] = sum_j W[j,m,k].   W: [256][256][256] fp32.
// (m,k) plane = 16384 float4 columns. 512 blocks x 32 cols; 8 j-groups x 32 j.
// Streaming loads (__ldcs): W is read exactly once, keep L2 for Wsum/o/out.
// ---------------------------------------------------------------------------
__global__ void __launch_bounds__(256) wsum_kernel(const float* __restrict__ W) {
    const int lane = threadIdx.x & 31;          // f4-col within block
    const int jg   = threadIdx.x >> 5;          // j-group 0..7
    const int col  = blockIdx.x * 32 + lane;    // global f4 column 0..16383

    const float4* __restrict__ W4 = (const float4*)W;
    float4 acc = make_float4(0.f, 0.f, 0.f, 0.f);
    const int j0 = jg * 32;
#pragma unroll 8
    for (int j = 0; j < 32; ++j) {
        float4 w = __ldcs(&W4[(size_t)(j0 + j) * 16384 + col]);
        acc.x += w.x; acc.y += w.y; acc.z += w.z; acc.w += w.w;
    }

    __shared__ float4 sh[256];
    sh[threadIdx.x] = acc;
    __syncthreads();

    if (jg == 0) {
        float4 r = sh[lane];
#pragma unroll
        for (int g = 1; g < 8; ++g) {
            float4 p = sh[g * 32 + lane];
            r.x += p.x; r.y += p.y; r.z += p.z; r.w += p.w;
        }
        ((float4*)g_wsum)[col] = r;
    }
}

// ---------------------------------------------------------------------------
// Kernel B: o[b,k]. 128 blocks x 4 batch rows; thread t == k.
// Each Wsum load feeds 4 accumulators -> 32 MB total L2 reads.
// ---------------------------------------------------------------------------
__global__ void __launch_bounds__(256) compute_o_kernel(const float* __restrict__ inputs) {
    const int b0 = blockIdx.x * 4;
    const int t  = threadIdx.x;  // k

    __shared__ float in_sh[4][256];
    __shared__ float red[4][8];

#pragma unroll
    for (int bb = 0; bb < 4; ++bb)
        in_sh[bb][t] = inputs[(b0 + bb) * 256 + t];
    __syncthreads();

    float acc0 = 0.f, acc1 = 0.f, acc2 = 0.f, acc3 = 0.f;
#pragma unroll 8
    for (int m = 0; m < 256; ++m) {
        const float w = g_wsum[m * 256 + t];
        acc0 = fmaf(in_sh[0][m], w, acc0);
        acc1 = fmaf(in_sh[1][m], w, acc1);
        acc2 = fmaf(in_sh[2][m], w, acc2);
        acc3 = fmaf(in_sh[3][m], w, acc3);
    }

    float v[4] = { acc0 * (1.f/256.f), acc1 * (1.f/256.f),
                   acc2 * (1.f/256.f), acc3 * (1.f/256.f) };

    // 4 block-wide sums of v^2 (deterministic shuffle + fixed combine)
#pragma unroll
    for (int bb = 0; bb < 4; ++bb) {
        float sq = v[bb] * v[bb];
#pragma unroll
        for (int o = 16; o > 0; o >>= 1)
            sq += __shfl_xor_sync(0xffffffffu, sq, o);
        if ((t & 31) == 0) red[bb][t >> 5] = sq;
    }
    __syncthreads();

#pragma unroll
    for (int bb = 0; bb < 4; ++bb) {
        const float* r = red[bb];
        const float s2 = ((r[0] + r[1]) + (r[2] + r[3])) +
                         ((r[4] + r[5]) + (r[6] + r[7]));
        const float scale = s2 / (1.0f + s2) / sqrtf(s2 + 1e-7f);
        g_o[(b0 + bb) * 256 + t] = scale * v[bb];
    }
}

// ---------------------------------------------------------------------------
// Kernel C: out[b,i,k] = o[b,k].  134 MB pure store stream.
// 4096 blocks = 512 b x 8 i-chunks of 32 rows. Thread t: col = t&63,
// base row = t>>6; 8 streaming float4 stores, fully coalesced.
// ---------------------------------------------------------------------------
__global__ void __launch_bounds__(256) broadcast_kernel(float* __restrict__ out) {
    const int b     = blockIdx.x >> 3;
    const int chunk = blockIdx.x & 7;          // 32 i-rows per chunk
    const int t     = threadIdx.x;
    const int col   = t & 63;
    const int r0    = t >> 6;                  // 0..3

    const float4 o4 = __ldg(&((const float4*)g_o)[b * 64 + col]);
    float4* __restrict__ dst = (float4*)out + (size_t)b * 16384
                               + (size_t)(chunk * 32) * 64 + col;
#pragma unroll
    for (int s = 0; s < 8; ++s)
        __stcs(dst + (size_t)(r0 + 4 * s) * 64, o4);
}

extern "C" void kernel_launch(void* const* d_in, const int* in_sizes, int n_in,
                              void* d_out, int out_size) {
    const float* inputs = (const float*)d_in[0];  // [512, 256]
    const float* W      = (const float*)d_in[1];  // [256, 256, 256]
    if (n_in >= 2 && in_sizes[0] > in_sizes[1]) {
        const float* tmp = inputs; inputs = W; W = tmp;
    }
    float* out = (float*)d_out;  // [512, 256, 256]

    wsum_kernel<<<512, 256>>>(W);
    compute_o_kernel<<<128, 256>>>(inputs);
    broadcast_kernel<<<4096, 256>>>(out);
    (void)out_size;
}

// round 6
// speedup vs baseline: 1.0139x; 1.0139x over previous
#include <cuda_runtime.h>

// Scratch: j-reduced weights and squashed per-batch output row.
__device__ float g_wsum[256 * 256];   // Wsum[m][k] = sum_j W[j][m][k]
__device__ float g_o[512 * 256];      // o[b][k] = squash_k(sum_m in[b,m]*Wsum[m,k]/256)

// ---------------------------------------------------------------------------
// Kernel A: Wsum[m,k] = sum_j W[j,m,k].   W: [256][256][256] fp32.
// (m,k) plane = 16384 float4 columns. 512 blocks x 32 cols; 8 j-groups x 32 j.
// Streaming loads (__ldcs): W is read exactly once, keep L2 for Wsum/o/out.
// ---------------------------------------------------------------------------
__global__ void __launch_bounds__(256) wsum_kernel(const float* __restrict__ W) {
    const int lane = threadIdx.x & 31;          // f4-col within block
    const int jg   = threadIdx.x >> 5;          // j-group 0..7
    const int col  = blockIdx.x * 32 + lane;    // global f4 column 0..16383

    const float4* __restrict__ W4 = (const float4*)W;
    float4 acc = make_float4(0.f, 0.f, 0.f, 0.f);
    const int j0 = jg * 32;
#pragma unroll 8
    for (int j = 0; j < 32; ++j) {
        float4 w = __ldcs(&W4[(size_t)(j0 + j) * 16384 + col]);
        acc.x += w.x; acc.y += w.y; acc.z += w.z; acc.w += w.w;
    }

    __shared__ float4 sh[256];
    sh[threadIdx.x] = acc;
    __syncthreads();

    if (jg == 0) {
        float4 r = sh[lane];
#pragma unroll
        for (int g = 1; g < 8; ++g) {
            float4 p = sh[g * 32 + lane];
            r.x += p.x; r.y += p.y; r.z += p.z; r.w += p.w;
        }
        ((float4*)g_wsum)[col] = r;
    }
}

// ---------------------------------------------------------------------------
// Kernel B: o[b,k]. 128 blocks x 4 batch rows; thread t == k.
// Each Wsum load feeds 4 accumulators -> 32 MB total L2 reads.
// ---------------------------------------------------------------------------
__global__ void __launch_bounds__(256) compute_o_kernel(const float* __restrict__ inputs) {
    const int b0 = blockIdx.x * 4;
    const int t  = threadIdx.x;  // k

    __shared__ float in_sh[4][256];
    __shared__ float red[4][8];

#pragma unroll
    for (int bb = 0; bb < 4; ++bb)
        in_sh[bb][t] = inputs[(b0 + bb) * 256 + t];
    __syncthreads();

    float acc0 = 0.f, acc1 = 0.f, acc2 = 0.f, acc3 = 0.f;
#pragma unroll 8
    for (int m = 0; m < 256; ++m) {
        const float w = g_wsum[m * 256 + t];
        acc0 = fmaf(in_sh[0][m], w, acc0);
        acc1 = fmaf(in_sh[1][m], w, acc1);
        acc2 = fmaf(in_sh[2][m], w, acc2);
        acc3 = fmaf(in_sh[3][m], w, acc3);
    }

    float v[4] = { acc0 * (1.f/256.f), acc1 * (1.f/256.f),
                   acc2 * (1.f/256.f), acc3 * (1.f/256.f) };

    // 4 block-wide sums of v^2 (deterministic shuffle + fixed combine)
#pragma unroll
    for (int bb = 0; bb < 4; ++bb) {
        float sq = v[bb] * v[bb];
#pragma unroll
        for (int o = 16; o > 0; o >>= 1)
            sq += __shfl_xor_sync(0xffffffffu, sq, o);
        if ((t & 31) == 0) red[bb][t >> 5] = sq;
    }
    __syncthreads();

#pragma unroll
    for (int bb = 0; bb < 4; ++bb) {
        const float* r = red[bb];
        const float s2 = ((r[0] + r[1]) + (r[2] + r[3])) +
                         ((r[4] + r[5]) + (r[6] + r[7]));
        const float scale = s2 / (1.0f + s2) / sqrtf(s2 + 1e-7f);
        g_o[(b0 + bb) * 256 + t] = scale * v[bb];
    }
}

// ---------------------------------------------------------------------------
// Kernel C: out[b,i,k] = o[b,k].  134 MB pure store stream.
// 4096 blocks = 512 b x 8 i-chunks of 32 rows. Thread t: col = t&63,
// base row = t>>6; 8 streaming float4 stores, fully coalesced.
// ---------------------------------------------------------------------------
__global__ void __launch_bounds__(256) broadcast_kernel(float* __restrict__ out) {
    const int b     = blockIdx.x >> 3;
    const int chunk = blockIdx.x & 7;          // 32 i-rows per chunk
    const int t     = threadIdx.x;
    const int col   = t & 63;
    const int r0    = t >> 6;                  // 0..3

    const float4 o4 = __ldg(&((const float4*)g_o)[b * 64 + col]);
    float4* __restrict__ dst = (float4*)out + (size_t)b * 16384
                               + (size_t)(chunk * 32) * 64 + col;
#pragma unroll
    for (int s = 0; s < 8; ++s)
        __stcs(dst + (size_t)(r0 + 4 * s) * 64, o4);
}

extern "C" void kernel_launch(void* const* d_in, const int* in_sizes, int n_in,
                              void* d_out, int out_size) {
    const float* inputs = (const float*)d_in[0];  // [512, 256]
    const float* W      = (const float*)d_in[1];  // [256, 256, 256]
    if (n_in >= 2 && in_sizes[0] > in_sizes[1]) {
        const float* tmp = inputs; inputs = W; W = tmp;
    }
    float* out = (float*)d_out;  // [512, 256, 256]

    wsum_kernel<<<512, 256>>>(W);
    compute_o_kernel<<<128, 256>>>(inputs);
    broadcast_kernel<<<4096, 256>>>(out);
    (void)out_size;
}